// round 1
// baseline (speedup 1.0000x reference)
#include <cuda_runtime.h>
#include <math_constants.h>

// Problem constants
#define S_LEN   2048
#define EMB     1024
#define NHEAD   16
#define HDIM    64
#define BATCH   4
#define MTOT    (BATCH * S_LEN)        // 8192
#define E3      (3 * EMB)              // 3072

// Scratch (device globals — no allocations allowed)
__device__ float g_qkv[(size_t)MTOT * E3];   // [M, 3072] : q|k|v per row
__device__ float g_att[(size_t)MTOT * EMB];  // [M, 1024] attention output (B,S,H*D)

// ---------------------------------------------------------------------------
// SGEMM (NT): C[m][n] = sum_k A[m][k] * B[n][k] + bias[n]
// A: [M,K] row-major, B: [N,K] row-major. 128x128x8 tile, 256 threads, 8x8/thread.
// Assumes M%128==0, N%128==0, K%8==0 (true for all calls here).
// ---------------------------------------------------------------------------
__global__ __launch_bounds__(256) void sgemm_nt_bias(
    const float* __restrict__ A, const float* __restrict__ B,
    const float* __restrict__ bias, float* __restrict__ C,
    int M, int N, int K)
{
    __shared__ float As[8][128];
    __shared__ float Bs[8][128];

    const int tid = threadIdx.x;
    const int bm  = blockIdx.y * 128;
    const int bn  = blockIdx.x * 128;

    const int lr = tid >> 1;            // 0..127 : row within tile for loads
    const int lk = (tid & 1) << 2;      // 0 or 4 : k offset for float4 load

    const int tx = tid & 15;            // 0..15
    const int ty = tid >> 4;            // 0..15

    const float* Ag = A + (size_t)(bm + lr) * K + lk;
    const float* Bg = B + (size_t)(bn + lr) * K + lk;

    float acc[8][8];
#pragma unroll
    for (int i = 0; i < 8; i++)
#pragma unroll
        for (int j = 0; j < 8; j++) acc[i][j] = 0.0f;

    for (int k0 = 0; k0 < K; k0 += 8) {
        float4 a = *(const float4*)(Ag + k0);
        float4 b = *(const float4*)(Bg + k0);
        As[lk + 0][lr] = a.x; As[lk + 1][lr] = a.y;
        As[lk + 2][lr] = a.z; As[lk + 3][lr] = a.w;
        Bs[lk + 0][lr] = b.x; Bs[lk + 1][lr] = b.y;
        Bs[lk + 2][lr] = b.z; Bs[lk + 3][lr] = b.w;
        __syncthreads();

#pragma unroll
        for (int k = 0; k < 8; k++) {
            float4 a0 = *(const float4*)&As[k][ty * 8];
            float4 a1 = *(const float4*)&As[k][ty * 8 + 4];
            float4 b0 = *(const float4*)&Bs[k][tx * 8];
            float4 b1 = *(const float4*)&Bs[k][tx * 8 + 4];
            float ra[8] = {a0.x, a0.y, a0.z, a0.w, a1.x, a1.y, a1.z, a1.w};
            float rb[8] = {b0.x, b0.y, b0.z, b0.w, b1.x, b1.y, b1.z, b1.w};
#pragma unroll
            for (int i = 0; i < 8; i++)
#pragma unroll
                for (int j = 0; j < 8; j++)
                    acc[i][j] = fmaf(ra[i], rb[j], acc[i][j]);
        }
        __syncthreads();
    }

#pragma unroll
    for (int i = 0; i < 8; i++) {
        const size_t row = (size_t)(bm + ty * 8 + i) * N + bn + tx * 8;
#pragma unroll
        for (int j = 0; j < 8; j++)
            C[row + j] = acc[i][j] + bias[bn + tx * 8 + j];
    }
}

// ---------------------------------------------------------------------------
// Causal flash attention. One block per (q-tile of 64, head, batch).
// Br = Bc = 64, 128 threads. Q/K stored transposed [d][row] in smem; V natural.
// Online softmax; O accumulator 8x4 per thread in registers.
// ---------------------------------------------------------------------------
#define LDP 68   // padded row stride (floats), keeps float4 alignment

__global__ __launch_bounds__(128) void attn_kernel(
    const float* __restrict__ qkv, float* __restrict__ out)
{
    extern __shared__ float sm[];
    float* Qs   = sm;                    // [64][LDP]  Qs[d][i]
    float* Ks   = Qs + 64 * LDP;         // [64][LDP]  Ks[d][j]
    float* Vs   = Ks + 64 * LDP;         // [64][LDP]  Vs[j][c]
    float* Ss   = Vs + 64 * LDP;         // [64][LDP]  Ss[i][j] (scores -> probs)
    float* mrow = Ss + 64 * LDP;         // [64]
    float* lrow = mrow + 64;             // [64]
    float* arow = lrow + 64;             // [64]

    const int qt  = blockIdx.x;          // q tile (0..31)
    const int h   = blockIdx.y;          // head
    const int b   = blockIdx.z;          // batch
    const int tid = threadIdx.x;         // 0..127
    const int tx  = tid & 15;
    const int ty  = tid >> 4;
    const int i0  = ty * 8;              // row block of this thread (8 rows)
    const int c0  = tx * 4;              // col block (4 cols)
    const float scale = 0.125f;          // 1/sqrt(64)

    const size_t rstride = (size_t)E3;
    const float* qbase = qkv + ((size_t)b * S_LEN + (size_t)qt * 64) * rstride + h * HDIM;

    // Load Q tile transposed: Qs[d][i]
#pragma unroll
    for (int it = 0; it < 8; it++) {
        int idx = tid + it * 128;
        int i   = idx >> 4;
        int d4  = (idx & 15) * 4;
        float4 v = *(const float4*)(qbase + (size_t)i * rstride + d4);
        Qs[(d4 + 0) * LDP + i] = v.x;
        Qs[(d4 + 1) * LDP + i] = v.y;
        Qs[(d4 + 2) * LDP + i] = v.z;
        Qs[(d4 + 3) * LDP + i] = v.w;
    }
    if (tid < 64) { mrow[tid] = -CUDART_INF_F; lrow[tid] = 0.0f; }

    float o_reg[8][4];
#pragma unroll
    for (int r = 0; r < 8; r++)
#pragma unroll
        for (int c = 0; c < 4; c++) o_reg[r][c] = 0.0f;

    for (int kt = 0; kt <= qt; kt++) {
        __syncthreads();  // protect smem tiles from previous iteration readers

        const float* kbase = qkv + ((size_t)b * S_LEN + (size_t)kt * 64) * rstride
                             + EMB + h * HDIM;
        const float* vbase = kbase + EMB;
#pragma unroll
        for (int it = 0; it < 8; it++) {
            int idx = tid + it * 128;
            int j   = idx >> 4;
            int d4  = (idx & 15) * 4;
            float4 kv = *(const float4*)(kbase + (size_t)j * rstride + d4);
            Ks[(d4 + 0) * LDP + j] = kv.x;
            Ks[(d4 + 1) * LDP + j] = kv.y;
            Ks[(d4 + 2) * LDP + j] = kv.z;
            Ks[(d4 + 3) * LDP + j] = kv.w;
            float4 vv = *(const float4*)(vbase + (size_t)j * rstride + d4);
            *(float4*)&Vs[j * LDP + d4] = vv;
        }
        __syncthreads();

        // S = scale * Q K^T   (8x4 microtile per thread)
        float acc[8][4];
#pragma unroll
        for (int r = 0; r < 8; r++)
#pragma unroll
            for (int c = 0; c < 4; c++) acc[r][c] = 0.0f;

#pragma unroll 4
        for (int d = 0; d < 64; d++) {
            float4 q0 = *(const float4*)&Qs[d * LDP + i0];
            float4 q1 = *(const float4*)&Qs[d * LDP + i0 + 4];
            float4 kk = *(const float4*)&Ks[d * LDP + c0];
            float qv[8] = {q0.x, q0.y, q0.z, q0.w, q1.x, q1.y, q1.z, q1.w};
            float kv[4] = {kk.x, kk.y, kk.z, kk.w};
#pragma unroll
            for (int r = 0; r < 8; r++)
#pragma unroll
                for (int c = 0; c < 4; c++)
                    acc[r][c] = fmaf(qv[r], kv[c], acc[r][c]);
        }

        // write scores (scale + causal mask on diagonal tile)
        const int ig0 = qt * 64 + i0;
        const int jg0 = kt * 64 + c0;
#pragma unroll
        for (int r = 0; r < 8; r++) {
#pragma unroll
            for (int c = 0; c < 4; c++) {
                float s = acc[r][c] * scale;
                if (kt == qt && (jg0 + c) > (ig0 + r)) s = -CUDART_INF_F;
                Ss[(i0 + r) * LDP + c0 + c] = s;
            }
        }
        __syncthreads();

        // online softmax row update (one thread per row)
        if (tid < 64) {
            float* srow = &Ss[tid * LDP];
            float tm = -CUDART_INF_F;
#pragma unroll 8
            for (int j = 0; j < 64; j++) tm = fmaxf(tm, srow[j]);
            float mold  = mrow[tid];
            float mnew  = fmaxf(mold, tm);     // finite: col j=0 never masked
            float alpha = __expf(mold - mnew); // -inf -> 0 on first tile
            float sum = 0.0f;
#pragma unroll 8
            for (int j = 0; j < 64; j++) {
                float p = __expf(srow[j] - mnew);
                srow[j] = p;
                sum += p;
            }
            lrow[tid] = lrow[tid] * alpha + sum;
            mrow[tid] = mnew;
            arow[tid] = alpha;
        }
        __syncthreads();

        // O = O*alpha + P V
#pragma unroll
        for (int r = 0; r < 8; r++) {
            float al = arow[i0 + r];
#pragma unroll
            for (int c = 0; c < 4; c++) o_reg[r][c] *= al;
        }
#pragma unroll 4
        for (int j = 0; j < 64; j++) {
            float4 vv = *(const float4*)&Vs[j * LDP + c0];
            float vr[4] = {vv.x, vv.y, vv.z, vv.w};
#pragma unroll
            for (int r = 0; r < 8; r++) {
                float p = Ss[(i0 + r) * LDP + j];
#pragma unroll
                for (int c = 0; c < 4; c++)
                    o_reg[r][c] = fmaf(p, vr[c], o_reg[r][c]);
            }
        }
    }

    // normalize + store: out layout [B, S, H*D]
    float* obase = out + ((size_t)b * S_LEN + (size_t)qt * 64) * EMB + h * HDIM;
#pragma unroll
    for (int r = 0; r < 8; r++) {
        float inv = 1.0f / lrow[i0 + r];
#pragma unroll
        for (int c = 0; c < 4; c++)
            obase[(size_t)(i0 + r) * EMB + c0 + c] = o_reg[r][c] * inv;
    }
}

// ---------------------------------------------------------------------------
// Launch
// ---------------------------------------------------------------------------
extern "C" void kernel_launch(void* const* d_in, const int* in_sizes, int n_in,
                              void* d_out, int out_size)
{
    const float* x     = (const float*)d_in[0];   // [4,2048,1024]
    const float* Wqkv  = (const float*)d_in[1];   // [3072,1024]
    const float* bqkv  = (const float*)d_in[2];   // [3072]
    const float* Wproj = (const float*)d_in[3];   // [1024,1024]
    const float* bproj = (const float*)d_in[4];   // [1024]
    float* out = (float*)d_out;                   // [4,2048,1024]

    float* qkv = nullptr;
    float* att = nullptr;
    cudaGetSymbolAddress((void**)&qkv, g_qkv);
    cudaGetSymbolAddress((void**)&att, g_att);

    const int smem_bytes = (4 * 64 * LDP + 3 * 64) * (int)sizeof(float); // 70400
    cudaFuncSetAttribute(attn_kernel,
                         cudaFuncAttributeMaxDynamicSharedMemorySize, smem_bytes);

    // 1) QKV GEMM: [8192,1024] @ [3072,1024]^T + b -> g_qkv [8192,3072]
    {
        dim3 grid(E3 / 128, MTOT / 128);
        sgemm_nt_bias<<<grid, 256>>>(x, Wqkv, bqkv, qkv, MTOT, E3, EMB);
    }
    // 2) causal flash attention -> g_att [8192,1024]
    {
        dim3 grid(S_LEN / 64, NHEAD, BATCH);
        attn_kernel<<<grid, 128, smem_bytes>>>(qkv, att);
    }
    // 3) proj GEMM: [8192,1024] @ [1024,1024]^T + b -> out
    {
        dim3 grid(EMB / 128, MTOT / 128);
        sgemm_nt_bias<<<grid, 256>>>(att, Wproj, bproj, out, MTOT, EMB, EMB);
    }
}

// round 3
// speedup vs baseline: 1.7363x; 1.7363x over previous
#include <cuda_runtime.h>
#include <math_constants.h>
#include <cstdint>

// Problem constants
#define S_LEN   2048
#define EMB     1024
#define NHEAD   16
#define HDIM    64
#define BATCH   4
#define MTOT    (BATCH * S_LEN)        // 8192
#define E3      (3 * EMB)              // 3072

// Scratch (device globals — no allocations allowed)
__device__ float g_qkv[(size_t)MTOT * E3];   // [M, 3072] : q|k|v per row
__device__ float g_att[(size_t)MTOT * EMB];  // [M, 1024] attention output (B,S,H*D)

// ===========================================================================
// tf32 mma.sync GEMM (NT): C[m][n] = sum_k A[m][k]*B[n][k] + bias[n]
// CTA tile 128x128, K-tile 32. 256 threads = 8 warps (2 warp-rows x 4 warp-cols),
// warp tile 64x32 via m16n8k8 tf32 mma. SMEM row stride 36 (conflict-free frags).
// Requires M%128==0, N%128==0, K%32==0.
// ===========================================================================
#define LDS_S       36
#define TILE_U32    (128 * LDS_S)      // 4608 words per tile

__device__ __forceinline__ uint32_t f2tf32(float f) {
    uint32_t u;
    asm("cvt.rna.tf32.f32 %0, %1;" : "=r"(u) : "f"(f));
    return u;
}

__device__ __forceinline__ void mma_tf32(float* d, const uint32_t* a, const uint32_t* b) {
    asm volatile(
        "mma.sync.aligned.m16n8k8.row.col.f32.tf32.tf32.f32 "
        "{%0,%1,%2,%3}, {%4,%5,%6,%7}, {%8,%9}, {%0,%1,%2,%3};"
        : "+f"(d[0]), "+f"(d[1]), "+f"(d[2]), "+f"(d[3])
        : "r"(a[0]), "r"(a[1]), "r"(a[2]), "r"(a[3]),
          "r"(b[0]), "r"(b[1]));
}

__global__ __launch_bounds__(256) void gemm_mma_tf32_nt_bias(
    const float* __restrict__ A, const float* __restrict__ B,
    const float* __restrict__ bias, float* __restrict__ C,
    int M, int N, int K)
{
    extern __shared__ uint32_t sm[];
    uint32_t* sA = sm;                      // [2][TILE_U32]
    uint32_t* sB = sm + 2 * TILE_U32;       // [2][TILE_U32]

    const int tid  = threadIdx.x;
    const int wid  = tid >> 5;
    const int lane = tid & 31;
    const int g    = lane >> 2;             // group 0..7
    const int t    = lane & 3;              // thread-in-group 0..3
    const int wm   = (wid & 1) * 64;        // warp row offset
    const int wn   = (wid >> 1) * 32;       // warp col offset
    const int bm   = blockIdx.y * 128;
    const int bn   = blockIdx.x * 128;

    // ---- loader lane mapping: 4 float4 per thread per tile ----
    const int lc4 = (tid & 7) * 4;          // k offset of float4
    int      lrow[4];
    uint32_t sto[4];
#pragma unroll
    for (int i = 0; i < 4; i++) {
        lrow[i] = (tid >> 3) + i * 32;
        sto[i]  = (uint32_t)(lrow[i] * LDS_S + lc4);
    }

    const int nk = K / 32;

    // ---- bias fragment (per-thread output columns), constant over k ----
    float bias0[4], bias1[4];
#pragma unroll
    for (int nt = 0; nt < 4; nt++) {
        int c = bn + wn + nt * 8 + 2 * t;
        bias0[nt] = bias[c];
        bias1[nt] = bias[c + 1];
    }

    float acc[4][4][4];
#pragma unroll
    for (int mt = 0; mt < 4; mt++)
#pragma unroll
        for (int nt = 0; nt < 4; nt++)
#pragma unroll
            for (int r = 0; r < 4; r++) acc[mt][nt][r] = 0.0f;

    // ---- preload k-tile 0 ----
    float4 ra[4], rb[4];
#pragma unroll
    for (int i = 0; i < 4; i++) {
        ra[i] = *(const float4*)(A + (size_t)(bm + lrow[i]) * K + lc4);
        rb[i] = *(const float4*)(B + (size_t)(bn + lrow[i]) * K + lc4);
    }
#pragma unroll
    for (int i = 0; i < 4; i++) {
        uint32_t* pa = sA + sto[i];
        uint32_t* pb = sB + sto[i];
        pa[0] = f2tf32(ra[i].x); pa[1] = f2tf32(ra[i].y);
        pa[2] = f2tf32(ra[i].z); pa[3] = f2tf32(ra[i].w);
        pb[0] = f2tf32(rb[i].x); pb[1] = f2tf32(rb[i].y);
        pb[2] = f2tf32(rb[i].z); pb[3] = f2tf32(rb[i].w);
    }
    __syncthreads();

    // per-warp fragment base offsets (word units)
    uint32_t aoff[4], boff[4];
#pragma unroll
    for (int mt = 0; mt < 4; mt++) aoff[mt] = (uint32_t)((wm + mt * 16 + g) * LDS_S + t);
#pragma unroll
    for (int nt = 0; nt < 4; nt++) boff[nt] = (uint32_t)((wn + nt * 8 + g) * LDS_S + t);

    for (int kt = 0; kt < nk; kt++) {
        const int cur  = kt & 1;
        const bool more = (kt + 1 < nk);
        if (more) {
            const int ko = (kt + 1) * 32 + lc4;
#pragma unroll
            for (int i = 0; i < 4; i++) {
                ra[i] = *(const float4*)(A + (size_t)(bm + lrow[i]) * K + ko);
                rb[i] = *(const float4*)(B + (size_t)(bn + lrow[i]) * K + ko);
            }
        }

        const uint32_t* As = sA + cur * TILE_U32;
        const uint32_t* Bs = sB + cur * TILE_U32;
#pragma unroll
        for (int kk = 0; kk < 32; kk += 8) {
            uint32_t af[4][4], bf[4][2];
#pragma unroll
            for (int mt = 0; mt < 4; mt++) {
                const uint32_t* p = As + aoff[mt] + kk;
                af[mt][0] = p[0];
                af[mt][1] = p[8 * LDS_S];
                af[mt][2] = p[4];
                af[mt][3] = p[8 * LDS_S + 4];
            }
#pragma unroll
            for (int nt = 0; nt < 4; nt++) {
                const uint32_t* p = Bs + boff[nt] + kk;
                bf[nt][0] = p[0];
                bf[nt][1] = p[4];
            }
#pragma unroll
            for (int mt = 0; mt < 4; mt++)
#pragma unroll
                for (int nt = 0; nt < 4; nt++)
                    mma_tf32(acc[mt][nt], af[mt], bf[nt]);
        }

        if (more) {
            __syncthreads();
            const int nxt = cur ^ 1;
            uint32_t* dA = sA + nxt * TILE_U32;
            uint32_t* dB = sB + nxt * TILE_U32;
#pragma unroll
            for (int i = 0; i < 4; i++) {
                uint32_t* pa = dA + sto[i];
                uint32_t* pb = dB + sto[i];
                pa[0] = f2tf32(ra[i].x); pa[1] = f2tf32(ra[i].y);
                pa[2] = f2tf32(ra[i].z); pa[3] = f2tf32(ra[i].w);
                pb[0] = f2tf32(rb[i].x); pb[1] = f2tf32(rb[i].y);
                pb[2] = f2tf32(rb[i].z); pb[3] = f2tf32(rb[i].w);
            }
            __syncthreads();
        }
    }

    // ---- epilogue: bias add + store ----
#pragma unroll
    for (int mt = 0; mt < 4; mt++) {
        const int r0 = bm + wm + mt * 16 + g;
#pragma unroll
        for (int nt = 0; nt < 4; nt++) {
            const int c0 = bn + wn + nt * 8 + 2 * t;
            float2 v0 = make_float2(acc[mt][nt][0] + bias0[nt],
                                    acc[mt][nt][1] + bias1[nt]);
            float2 v1 = make_float2(acc[mt][nt][2] + bias0[nt],
                                    acc[mt][nt][3] + bias1[nt]);
            *(float2*)(C + (size_t)r0 * N + c0)       = v0;
            *(float2*)(C + (size_t)(r0 + 8) * N + c0) = v1;
        }
    }
}

#define GEMM_SMEM (4 * TILE_U32 * (int)sizeof(uint32_t))   // 73728 B

// ===========================================================================
// Causal flash attention (unchanged from R1). One block per (q-tile 64, h, b).
// ===========================================================================
#define LDP 68

__global__ __launch_bounds__(128) void attn_kernel(
    const float* __restrict__ qkv, float* __restrict__ out)
{
    extern __shared__ float smf[];
    float* Qs   = smf;
    float* Ks   = Qs + 64 * LDP;
    float* Vs   = Ks + 64 * LDP;
    float* Ss   = Vs + 64 * LDP;
    float* mrow = Ss + 64 * LDP;
    float* lrow = mrow + 64;
    float* arow = lrow + 64;

    const int qt  = blockIdx.x;
    const int h   = blockIdx.y;
    const int b   = blockIdx.z;
    const int tid = threadIdx.x;
    const int tx  = tid & 15;
    const int ty  = tid >> 4;
    const int i0  = ty * 8;
    const int c0  = tx * 4;
    const float scale = 0.125f;

    const size_t rstride = (size_t)E3;
    const float* qbase = qkv + ((size_t)b * S_LEN + (size_t)qt * 64) * rstride + h * HDIM;

#pragma unroll
    for (int it = 0; it < 8; it++) {
        int idx = tid + it * 128;
        int i   = idx >> 4;
        int d4  = (idx & 15) * 4;
        float4 v = *(const float4*)(qbase + (size_t)i * rstride + d4);
        Qs[(d4 + 0) * LDP + i] = v.x;
        Qs[(d4 + 1) * LDP + i] = v.y;
        Qs[(d4 + 2) * LDP + i] = v.z;
        Qs[(d4 + 3) * LDP + i] = v.w;
    }
    if (tid < 64) { mrow[tid] = -CUDART_INF_F; lrow[tid] = 0.0f; }

    float o_reg[8][4];
#pragma unroll
    for (int r = 0; r < 8; r++)
#pragma unroll
        for (int c = 0; c < 4; c++) o_reg[r][c] = 0.0f;

    for (int kt = 0; kt <= qt; kt++) {
        __syncthreads();

        const float* kbase = qkv + ((size_t)b * S_LEN + (size_t)kt * 64) * rstride
                             + EMB + h * HDIM;
        const float* vbase = kbase + EMB;
#pragma unroll
        for (int it = 0; it < 8; it++) {
            int idx = tid + it * 128;
            int j   = idx >> 4;
            int d4  = (idx & 15) * 4;
            float4 kv = *(const float4*)(kbase + (size_t)j * rstride + d4);
            Ks[(d4 + 0) * LDP + j] = kv.x;
            Ks[(d4 + 1) * LDP + j] = kv.y;
            Ks[(d4 + 2) * LDP + j] = kv.z;
            Ks[(d4 + 3) * LDP + j] = kv.w;
            float4 vv = *(const float4*)(vbase + (size_t)j * rstride + d4);
            *(float4*)&Vs[j * LDP + d4] = vv;
        }
        __syncthreads();

        float acc[8][4];
#pragma unroll
        for (int r = 0; r < 8; r++)
#pragma unroll
            for (int c = 0; c < 4; c++) acc[r][c] = 0.0f;

#pragma unroll 4
        for (int d = 0; d < 64; d++) {
            float4 q0 = *(const float4*)&Qs[d * LDP + i0];
            float4 q1 = *(const float4*)&Qs[d * LDP + i0 + 4];
            float4 kk = *(const float4*)&Ks[d * LDP + c0];
            float qv[8] = {q0.x, q0.y, q0.z, q0.w, q1.x, q1.y, q1.z, q1.w};
            float kv[4] = {kk.x, kk.y, kk.z, kk.w};
#pragma unroll
            for (int r = 0; r < 8; r++)
#pragma unroll
                for (int c = 0; c < 4; c++)
                    acc[r][c] = fmaf(qv[r], kv[c], acc[r][c]);
        }

        const int ig0 = qt * 64 + i0;
        const int jg0 = kt * 64 + c0;
#pragma unroll
        for (int r = 0; r < 8; r++) {
#pragma unroll
            for (int c = 0; c < 4; c++) {
                float s = acc[r][c] * scale;
                if (kt == qt && (jg0 + c) > (ig0 + r)) s = -CUDART_INF_F;
                Ss[(i0 + r) * LDP + c0 + c] = s;
            }
        }
        __syncthreads();

        if (tid < 64) {
            float* srow = &Ss[tid * LDP];
            float tm = -CUDART_INF_F;
#pragma unroll 8
            for (int j = 0; j < 64; j++) tm = fmaxf(tm, srow[j]);
            float mold  = mrow[tid];
            float mnew  = fmaxf(mold, tm);
            float alpha = __expf(mold - mnew);
            float sum = 0.0f;
#pragma unroll 8
            for (int j = 0; j < 64; j++) {
                float p = __expf(srow[j] - mnew);
                srow[j] = p;
                sum += p;
            }
            lrow[tid] = lrow[tid] * alpha + sum;
            mrow[tid] = mnew;
            arow[tid] = alpha;
        }
        __syncthreads();

#pragma unroll
        for (int r = 0; r < 8; r++) {
            float al = arow[i0 + r];
#pragma unroll
            for (int c = 0; c < 4; c++) o_reg[r][c] *= al;
        }
#pragma unroll 4
        for (int j = 0; j < 64; j++) {
            float4 vv = *(const float4*)&Vs[j * LDP + c0];
            float vr[4] = {vv.x, vv.y, vv.z, vv.w};
#pragma unroll
            for (int r = 0; r < 8; r++) {
                float p = Ss[(i0 + r) * LDP + j];
#pragma unroll
                for (int c = 0; c < 4; c++)
                    o_reg[r][c] = fmaf(p, vr[c], o_reg[r][c]);
            }
        }
    }

    float* obase = out + ((size_t)b * S_LEN + (size_t)qt * 64) * EMB + h * HDIM;
#pragma unroll
    for (int r = 0; r < 8; r++) {
        float inv = 1.0f / lrow[i0 + r];
#pragma unroll
        for (int c = 0; c < 4; c++)
            obase[(size_t)(i0 + r) * EMB + c0 + c] = o_reg[r][c] * inv;
    }
}

// ===========================================================================
// Launch
// ===========================================================================
extern "C" void kernel_launch(void* const* d_in, const int* in_sizes, int n_in,
                              void* d_out, int out_size)
{
    const float* x     = (const float*)d_in[0];   // [4,2048,1024]
    const float* Wqkv  = (const float*)d_in[1];   // [3072,1024]
    const float* bqkv  = (const float*)d_in[2];   // [3072]
    const float* Wproj = (const float*)d_in[3];   // [1024,1024]
    const float* bproj = (const float*)d_in[4];   // [1024]
    float* out = (float*)d_out;                   // [4,2048,1024]

    float* qkv = nullptr;
    float* att = nullptr;
    cudaGetSymbolAddress((void**)&qkv, g_qkv);
    cudaGetSymbolAddress((void**)&att, g_att);

    cudaFuncSetAttribute(gemm_mma_tf32_nt_bias,
                         cudaFuncAttributeMaxDynamicSharedMemorySize, GEMM_SMEM);
    const int attn_smem = (4 * 64 * LDP + 3 * 64) * (int)sizeof(float);
    cudaFuncSetAttribute(attn_kernel,
                         cudaFuncAttributeMaxDynamicSharedMemorySize, attn_smem);

    // 1) QKV GEMM (tf32 mma): [8192,1024] @ [3072,1024]^T + b -> g_qkv
    {
        dim3 grid(E3 / 128, MTOT / 128);
        gemm_mma_tf32_nt_bias<<<grid, 256, GEMM_SMEM>>>(x, Wqkv, bqkv, qkv, MTOT, E3, EMB);
    }
    // 2) causal flash attention -> g_att
    {
        dim3 grid(S_LEN / 64, NHEAD, BATCH);
        attn_kernel<<<grid, 128, attn_smem>>>(qkv, att);
    }
    // 3) proj GEMM (tf32 mma): [8192,1024] @ [1024,1024]^T + b -> out
    {
        dim3 grid(EMB / 128, MTOT / 128);
        gemm_mma_tf32_nt_bias<<<grid, 256, GEMM_SMEM>>>(att, Wproj, bproj, out, MTOT, EMB, EMB);
    }
}

// round 4
// speedup vs baseline: 2.9867x; 1.7201x over previous
#include <cuda_runtime.h>
#include <math_constants.h>
#include <cstdint>

// Problem constants
#define S_LEN   2048
#define EMB     1024
#define NHEAD   16
#define HDIM    64
#define BATCH   4
#define MTOT    (BATCH * S_LEN)        // 8192
#define E3      (3 * EMB)              // 3072

// Scratch (device globals — no allocations allowed)
__device__ float g_qkv[(size_t)MTOT * E3];   // [M, 3072] : q|k|v per row
__device__ float g_att[(size_t)MTOT * EMB];  // [M, 1024] attention output (B,S,H*D)

__device__ __forceinline__ uint32_t f2tf32(float f) {
    uint32_t u;
    asm("cvt.rna.tf32.f32 %0, %1;" : "=r"(u) : "f"(f));
    return u;
}

__device__ __forceinline__ void mma_tf32(float* d, const uint32_t* a, const uint32_t* b) {
    asm volatile(
        "mma.sync.aligned.m16n8k8.row.col.f32.tf32.tf32.f32 "
        "{%0,%1,%2,%3}, {%4,%5,%6,%7}, {%8,%9}, {%0,%1,%2,%3};"
        : "+f"(d[0]), "+f"(d[1]), "+f"(d[2]), "+f"(d[3])
        : "r"(a[0]), "r"(a[1]), "r"(a[2]), "r"(a[3]),
          "r"(b[0]), "r"(b[1]));
}

// ===========================================================================
// tf32 mma.sync GEMM (NT) — unchanged from R3 (passing, 434us QKV).
// ===========================================================================
#define LDS_S       36
#define TILE_U32    (128 * LDS_S)

__global__ __launch_bounds__(256) void gemm_mma_tf32_nt_bias(
    const float* __restrict__ A, const float* __restrict__ B,
    const float* __restrict__ bias, float* __restrict__ C,
    int M, int N, int K)
{
    extern __shared__ uint32_t sm[];
    uint32_t* sA = sm;
    uint32_t* sB = sm + 2 * TILE_U32;

    const int tid  = threadIdx.x;
    const int wid  = tid >> 5;
    const int lane = tid & 31;
    const int g    = lane >> 2;
    const int t    = lane & 3;
    const int wm   = (wid & 1) * 64;
    const int wn   = (wid >> 1) * 32;
    const int bm   = blockIdx.y * 128;
    const int bn   = blockIdx.x * 128;

    const int lc4 = (tid & 7) * 4;
    int      lrow[4];
    uint32_t sto[4];
#pragma unroll
    for (int i = 0; i < 4; i++) {
        lrow[i] = (tid >> 3) + i * 32;
        sto[i]  = (uint32_t)(lrow[i] * LDS_S + lc4);
    }

    const int nk = K / 32;

    float bias0[4], bias1[4];
#pragma unroll
    for (int nt = 0; nt < 4; nt++) {
        int c = bn + wn + nt * 8 + 2 * t;
        bias0[nt] = bias[c];
        bias1[nt] = bias[c + 1];
    }

    float acc[4][4][4];
#pragma unroll
    for (int mt = 0; mt < 4; mt++)
#pragma unroll
        for (int nt = 0; nt < 4; nt++)
#pragma unroll
            for (int r = 0; r < 4; r++) acc[mt][nt][r] = 0.0f;

    float4 ra[4], rb[4];
#pragma unroll
    for (int i = 0; i < 4; i++) {
        ra[i] = *(const float4*)(A + (size_t)(bm + lrow[i]) * K + lc4);
        rb[i] = *(const float4*)(B + (size_t)(bn + lrow[i]) * K + lc4);
    }
#pragma unroll
    for (int i = 0; i < 4; i++) {
        uint32_t* pa = sA + sto[i];
        uint32_t* pb = sB + sto[i];
        pa[0] = f2tf32(ra[i].x); pa[1] = f2tf32(ra[i].y);
        pa[2] = f2tf32(ra[i].z); pa[3] = f2tf32(ra[i].w);
        pb[0] = f2tf32(rb[i].x); pb[1] = f2tf32(rb[i].y);
        pb[2] = f2tf32(rb[i].z); pb[3] = f2tf32(rb[i].w);
    }
    __syncthreads();

    uint32_t aoff[4], boff[4];
#pragma unroll
    for (int mt = 0; mt < 4; mt++) aoff[mt] = (uint32_t)((wm + mt * 16 + g) * LDS_S + t);
#pragma unroll
    for (int nt = 0; nt < 4; nt++) boff[nt] = (uint32_t)((wn + nt * 8 + g) * LDS_S + t);

    for (int kt = 0; kt < nk; kt++) {
        const int cur  = kt & 1;
        const bool more = (kt + 1 < nk);
        if (more) {
            const int ko = (kt + 1) * 32 + lc4;
#pragma unroll
            for (int i = 0; i < 4; i++) {
                ra[i] = *(const float4*)(A + (size_t)(bm + lrow[i]) * K + ko);
                rb[i] = *(const float4*)(B + (size_t)(bn + lrow[i]) * K + ko);
            }
        }

        const uint32_t* As = sA + cur * TILE_U32;
        const uint32_t* Bs = sB + cur * TILE_U32;
#pragma unroll
        for (int kk = 0; kk < 32; kk += 8) {
            uint32_t af[4][4], bf[4][2];
#pragma unroll
            for (int mt = 0; mt < 4; mt++) {
                const uint32_t* p = As + aoff[mt] + kk;
                af[mt][0] = p[0];
                af[mt][1] = p[8 * LDS_S];
                af[mt][2] = p[4];
                af[mt][3] = p[8 * LDS_S + 4];
            }
#pragma unroll
            for (int nt = 0; nt < 4; nt++) {
                const uint32_t* p = Bs + boff[nt] + kk;
                bf[nt][0] = p[0];
                bf[nt][1] = p[4];
            }
#pragma unroll
            for (int mt = 0; mt < 4; mt++)
#pragma unroll
                for (int nt = 0; nt < 4; nt++)
                    mma_tf32(acc[mt][nt], af[mt], bf[nt]);
        }

        if (more) {
            __syncthreads();
            const int nxt = cur ^ 1;
            uint32_t* dA = sA + nxt * TILE_U32;
            uint32_t* dB = sB + nxt * TILE_U32;
#pragma unroll
            for (int i = 0; i < 4; i++) {
                uint32_t* pa = dA + sto[i];
                uint32_t* pb = dB + sto[i];
                pa[0] = f2tf32(ra[i].x); pa[1] = f2tf32(ra[i].y);
                pa[2] = f2tf32(ra[i].z); pa[3] = f2tf32(ra[i].w);
                pb[0] = f2tf32(rb[i].x); pb[1] = f2tf32(rb[i].y);
                pb[2] = f2tf32(rb[i].z); pb[3] = f2tf32(rb[i].w);
            }
            __syncthreads();
        }
    }

#pragma unroll
    for (int mt = 0; mt < 4; mt++) {
        const int r0 = bm + wm + mt * 16 + g;
#pragma unroll
        for (int nt = 0; nt < 4; nt++) {
            const int c0 = bn + wn + nt * 8 + 2 * t;
            float2 v0 = make_float2(acc[mt][nt][0] + bias0[nt],
                                    acc[mt][nt][1] + bias1[nt]);
            float2 v1 = make_float2(acc[mt][nt][2] + bias0[nt],
                                    acc[mt][nt][3] + bias1[nt]);
            *(float2*)(C + (size_t)r0 * N + c0)       = v0;
            *(float2*)(C + (size_t)(r0 + 8) * N + c0) = v1;
        }
    }
}

#define GEMM_SMEM (4 * TILE_U32 * (int)sizeof(uint32_t))   // 73728 B

// ===========================================================================
// Tensor-core causal flash attention.
// One block per (q-tile 64, head, batch). 128 threads = 4 warps.
// Warp tile: 16 q-rows x 64 kv-cols of S, via m16n8k8 tf32 mma.
// Q fragments live in registers for the whole loop. Online softmax in
// fragments (quad shuffles). P round-trips through warp-private smem to
// re-fragment for PV.
// Strides (words): Ks 68 (bank=4g+t bijective), Vs 72 (bank=8t+g bijective),
// Ss/P 68.
// ===========================================================================
#define LDK 68
#define LDV 72
#define LDSP 68
#define ATTN_SMEM ((64 * LDK + 64 * LDV + 64 * LDSP) * (int)sizeof(uint32_t)) // 53248

__global__ __launch_bounds__(128) void attn_mma_kernel(
    const float* __restrict__ qkv, float* __restrict__ out)
{
    extern __shared__ uint32_t smw[];
    uint32_t* Ks = smw;                   // [64][LDK]  K[n][d] tf32
    uint32_t* Vs = Ks + 64 * LDK;         // [64][LDV]  V[k][d] tf32
    uint32_t* Ss = Vs + 64 * LDV;         // [64][LDSP] Q stage, then P (tf32)

    const int qt   = blockIdx.x;
    const int h    = blockIdx.y;
    const int b    = blockIdx.z;
    const int tid  = threadIdx.x;
    const int wid  = tid >> 5;
    const int lane = tid & 31;
    const int g    = lane >> 2;
    const int t    = lane & 3;
    const int r0   = wid * 16;            // warp's q-row base within tile
    const float scale = 0.125f;
    const size_t rstride = (size_t)E3;

    // ---- stage Q tile (tf32) into Ss, then grab fragments ----
    const float* qbase = qkv + ((size_t)b * S_LEN + (size_t)qt * 64) * rstride + h * HDIM;
#pragma unroll
    for (int i = 0; i < 8; i++) {
        int idx = tid + i * 128;
        int row = idx >> 4;
        int c4  = (idx & 15) * 4;
        float4 v = *(const float4*)(qbase + (size_t)row * rstride + c4);
        uint32_t* p = Ss + row * LDSP + c4;
        p[0] = f2tf32(v.x); p[1] = f2tf32(v.y);
        p[2] = f2tf32(v.z); p[3] = f2tf32(v.w);
    }
    __syncthreads();

    uint32_t qf[8][4];
#pragma unroll
    for (int ks = 0; ks < 8; ks++) {
        const uint32_t* p0 = Ss + (r0 + g) * LDSP + ks * 8 + t;
        const uint32_t* p1 = Ss + (r0 + g + 8) * LDSP + ks * 8 + t;
        qf[ks][0] = p0[0];
        qf[ks][1] = p1[0];
        qf[ks][2] = p0[4];
        qf[ks][3] = p1[4];
    }

    float m_lo = -CUDART_INF_F, m_hi = -CUDART_INF_F;
    float l_lo = 0.0f, l_hi = 0.0f;
    float oacc[8][4];
#pragma unroll
    for (int nt = 0; nt < 8; nt++)
#pragma unroll
        for (int r = 0; r < 4; r++) oacc[nt][r] = 0.0f;

    for (int kt = 0; kt <= qt; kt++) {
        __syncthreads();   // protect Ks/Vs (and first iter: Q-frag reads of Ss)

        // ---- load K,V tiles (convert to tf32) ----
        const float* kbase = qkv + ((size_t)b * S_LEN + (size_t)kt * 64) * rstride
                             + EMB + h * HDIM;
        const float* vbase = kbase + EMB;
#pragma unroll
        for (int i = 0; i < 8; i++) {
            int idx = tid + i * 128;
            int row = idx >> 4;
            int c4  = (idx & 15) * 4;
            float4 kv = *(const float4*)(kbase + (size_t)row * rstride + c4);
            uint32_t* pk = Ks + row * LDK + c4;
            pk[0] = f2tf32(kv.x); pk[1] = f2tf32(kv.y);
            pk[2] = f2tf32(kv.z); pk[3] = f2tf32(kv.w);
            float4 vv = *(const float4*)(vbase + (size_t)row * rstride + c4);
            uint32_t* pv = Vs + row * LDV + c4;
            pv[0] = f2tf32(vv.x); pv[1] = f2tf32(vv.y);
            pv[2] = f2tf32(vv.z); pv[3] = f2tf32(vv.w);
        }
        __syncthreads();

        // ---- S = Q K^T (warp: 16x64) ----
        float sacc[8][4];
#pragma unroll
        for (int nt = 0; nt < 8; nt++)
#pragma unroll
            for (int r = 0; r < 4; r++) sacc[nt][r] = 0.0f;

#pragma unroll
        for (int ks = 0; ks < 8; ks++) {
            const int kk = ks * 8;
#pragma unroll
            for (int nt = 0; nt < 8; nt++) {
                const uint32_t* pb = Ks + (nt * 8 + g) * LDK + kk + t;
                uint32_t bf[2] = { pb[0], pb[4] };
                mma_tf32(sacc[nt], qf[ks], bf);
            }
        }

        // ---- scale + causal mask (diagonal tile only) ----
        const bool diag = (kt == qt);
#pragma unroll
        for (int nt = 0; nt < 8; nt++) {
            const int c0 = nt * 8 + 2 * t;
#pragma unroll
            for (int r = 0; r < 4; r++) sacc[nt][r] *= scale;
            if (diag) {
                const int rlo = r0 + g, rhi = r0 + g + 8;
                if (c0 + 0 > rlo) sacc[nt][0] = -CUDART_INF_F;
                if (c0 + 1 > rlo) sacc[nt][1] = -CUDART_INF_F;
                if (c0 + 0 > rhi) sacc[nt][2] = -CUDART_INF_F;
                if (c0 + 1 > rhi) sacc[nt][3] = -CUDART_INF_F;
            }
        }

        // ---- row max (thread-local then quad shuffle) ----
        float tmax_lo = -CUDART_INF_F, tmax_hi = -CUDART_INF_F;
#pragma unroll
        for (int nt = 0; nt < 8; nt++) {
            tmax_lo = fmaxf(tmax_lo, fmaxf(sacc[nt][0], sacc[nt][1]));
            tmax_hi = fmaxf(tmax_hi, fmaxf(sacc[nt][2], sacc[nt][3]));
        }
        tmax_lo = fmaxf(tmax_lo, __shfl_xor_sync(0xFFFFFFFF, tmax_lo, 1));
        tmax_lo = fmaxf(tmax_lo, __shfl_xor_sync(0xFFFFFFFF, tmax_lo, 2));
        tmax_hi = fmaxf(tmax_hi, __shfl_xor_sync(0xFFFFFFFF, tmax_hi, 1));
        tmax_hi = fmaxf(tmax_hi, __shfl_xor_sync(0xFFFFFFFF, tmax_hi, 2));

        const float mnew_lo = fmaxf(m_lo, tmax_lo);
        const float mnew_hi = fmaxf(m_hi, tmax_hi);
        const float alpha_lo = __expf(m_lo - mnew_lo);
        const float alpha_hi = __expf(m_hi - mnew_hi);

        // ---- exp, write P (tf32) to warp-private smem, accumulate sums ----
        float sum_lo = 0.0f, sum_hi = 0.0f;
        uint32_t* prow0 = Ss + (r0 + g) * LDSP;
        uint32_t* prow1 = Ss + (r0 + g + 8) * LDSP;
#pragma unroll
        for (int nt = 0; nt < 8; nt++) {
            const int c0 = nt * 8 + 2 * t;
            float p0 = __expf(sacc[nt][0] - mnew_lo);
            float p1 = __expf(sacc[nt][1] - mnew_lo);
            float p2 = __expf(sacc[nt][2] - mnew_hi);
            float p3 = __expf(sacc[nt][3] - mnew_hi);
            sum_lo += p0 + p1;
            sum_hi += p2 + p3;
            uint2 u0 = make_uint2(f2tf32(p0), f2tf32(p1));
            uint2 u1 = make_uint2(f2tf32(p2), f2tf32(p3));
            *(uint2*)(prow0 + c0) = u0;
            *(uint2*)(prow1 + c0) = u1;
        }
        sum_lo += __shfl_xor_sync(0xFFFFFFFF, sum_lo, 1);
        sum_lo += __shfl_xor_sync(0xFFFFFFFF, sum_lo, 2);
        sum_hi += __shfl_xor_sync(0xFFFFFFFF, sum_hi, 1);
        sum_hi += __shfl_xor_sync(0xFFFFFFFF, sum_hi, 2);

        l_lo = l_lo * alpha_lo + sum_lo;
        l_hi = l_hi * alpha_hi + sum_hi;
        m_lo = mnew_lo;
        m_hi = mnew_hi;

        // ---- rescale O ----
#pragma unroll
        for (int nt = 0; nt < 8; nt++) {
            oacc[nt][0] *= alpha_lo;
            oacc[nt][1] *= alpha_lo;
            oacc[nt][2] *= alpha_hi;
            oacc[nt][3] *= alpha_hi;
        }

        __syncwarp();   // P writes visible to all lanes of this warp

        // ---- O += P V ----
#pragma unroll
        for (int ks = 0; ks < 8; ks++) {
            const int kk = ks * 8;
            const uint32_t* pa0 = Ss + (r0 + g) * LDSP + kk + t;
            const uint32_t* pa1 = Ss + (r0 + g + 8) * LDSP + kk + t;
            uint32_t af[4] = { pa0[0], pa1[0], pa0[4], pa1[4] };
#pragma unroll
            for (int nt = 0; nt < 8; nt++) {
                const uint32_t* pb = Vs + (kk + t) * LDV + nt * 8 + g;
                uint32_t bf[2] = { pb[0], pb[4 * LDV] };
                mma_tf32(oacc[nt], af, bf);
            }
        }
        // next-iteration __syncthreads orders these reads vs. future writes
    }

    // ---- epilogue: normalize + store ----
    const float inv_lo = 1.0f / l_lo;
    const float inv_hi = 1.0f / l_hi;
    float* obase = out + ((size_t)b * S_LEN + (size_t)qt * 64) * EMB + h * HDIM;
    float* orow0 = obase + (size_t)(r0 + g) * EMB;
    float* orow1 = obase + (size_t)(r0 + g + 8) * EMB;
#pragma unroll
    for (int nt = 0; nt < 8; nt++) {
        const int c0 = nt * 8 + 2 * t;
        *(float2*)(orow0 + c0) = make_float2(oacc[nt][0] * inv_lo, oacc[nt][1] * inv_lo);
        *(float2*)(orow1 + c0) = make_float2(oacc[nt][2] * inv_hi, oacc[nt][3] * inv_hi);
    }
}

// ===========================================================================
// Launch
// ===========================================================================
extern "C" void kernel_launch(void* const* d_in, const int* in_sizes, int n_in,
                              void* d_out, int out_size)
{
    const float* x     = (const float*)d_in[0];   // [4,2048,1024]
    const float* Wqkv  = (const float*)d_in[1];   // [3072,1024]
    const float* bqkv  = (const float*)d_in[2];   // [3072]
    const float* Wproj = (const float*)d_in[3];   // [1024,1024]
    const float* bproj = (const float*)d_in[4];   // [1024]
    float* out = (float*)d_out;                   // [4,2048,1024]

    float* qkv = nullptr;
    float* att = nullptr;
    cudaGetSymbolAddress((void**)&qkv, g_qkv);
    cudaGetSymbolAddress((void**)&att, g_att);

    cudaFuncSetAttribute(gemm_mma_tf32_nt_bias,
                         cudaFuncAttributeMaxDynamicSharedMemorySize, GEMM_SMEM);
    cudaFuncSetAttribute(attn_mma_kernel,
                         cudaFuncAttributeMaxDynamicSharedMemorySize, ATTN_SMEM);

    // 1) QKV GEMM (tf32 mma): [8192,1024] @ [3072,1024]^T + b -> g_qkv
    {
        dim3 grid(E3 / 128, MTOT / 128);
        gemm_mma_tf32_nt_bias<<<grid, 256, GEMM_SMEM>>>(x, Wqkv, bqkv, qkv, MTOT, E3, EMB);
    }
    // 2) causal flash attention (tensor cores) -> g_att
    {
        dim3 grid(S_LEN / 64, NHEAD, BATCH);
        attn_mma_kernel<<<grid, 128, ATTN_SMEM>>>(qkv, att);
    }
    // 3) proj GEMM (tf32 mma): [8192,1024] @ [1024,1024]^T + b -> out
    {
        dim3 grid(EMB / 128, MTOT / 128);
        gemm_mma_tf32_nt_bias<<<grid, 256, GEMM_SMEM>>>(att, Wproj, bproj, out, MTOT, EMB, EMB);
    }
}

// round 5
// speedup vs baseline: 3.2528x; 1.0891x over previous
#include <cuda_runtime.h>
#include <math_constants.h>
#include <cstdint>

// Problem constants
#define S_LEN   2048
#define EMB     1024
#define NHEAD   16
#define HDIM    64
#define BATCH   4
#define MTOT    (BATCH * S_LEN)        // 8192
#define E3      (3 * EMB)              // 3072

// Scratch (device globals — no allocations allowed)
__device__ float g_qkv[(size_t)MTOT * E3];   // [M, 3072] : q|k|v per row
__device__ float g_att[(size_t)MTOT * EMB];  // [M, 1024] attention output (B,S,H*D)

__device__ __forceinline__ uint32_t f2tf32(float f) {
    uint32_t u;
    asm("cvt.rna.tf32.f32 %0, %1;" : "=r"(u) : "f"(f));
    return u;
}

__device__ __forceinline__ void mma_tf32(float* d, const uint32_t* a, const uint32_t* b) {
    asm volatile(
        "mma.sync.aligned.m16n8k8.row.col.f32.tf32.tf32.f32 "
        "{%0,%1,%2,%3}, {%4,%5,%6,%7}, {%8,%9}, {%0,%1,%2,%3};"
        : "+f"(d[0]), "+f"(d[1]), "+f"(d[2]), "+f"(d[3])
        : "r"(a[0]), "r"(a[1]), "r"(a[2]), "r"(a[3]),
          "r"(b[0]), "r"(b[1]));
}

__device__ __forceinline__ uint32_t smem_u32(const void* p) {
    uint32_t a;
    asm("{ .reg .u64 t; cvta.to.shared.u64 t, %1; cvt.u32.u64 %0, t; }"
        : "=r"(a) : "l"(p));
    return a;
}

#define CP_ASYNC16(dst_u32, src_ptr) \
    asm volatile("cp.async.cg.shared.global [%0], [%1], 16;" \
                 :: "r"(dst_u32), "l"(src_ptr))
#define CP_COMMIT()  asm volatile("cp.async.commit_group;" ::: "memory")
#define CP_WAIT0()   asm volatile("cp.async.wait_group 0;" ::: "memory")

// ===========================================================================
// tf32 mma.sync GEMM (NT): C = A B^T + bias. CTA tile 128x128, K-tile 32,
// 256 threads = 8 warps (warp tile 64x32). Double-buffered cp.async (raw
// fp32 in smem); cvt.rna.tf32 applied post-LDS on fragments. 2 CTAs/SM.
// Requires M%128==0, N%128==0, K%32==0.
// ===========================================================================
#define LDS_S       36
#define TILE_U32    (128 * LDS_S)
#define GEMM_SMEM   (4 * TILE_U32 * (int)sizeof(uint32_t))   // 73728 B

__global__ __launch_bounds__(256, 2) void gemm_mma_tf32_nt_bias(
    const float* __restrict__ A, const float* __restrict__ B,
    const float* __restrict__ bias, float* __restrict__ C,
    int M, int N, int K)
{
    extern __shared__ float smf[];
    float* sA = smf;                      // [2][TILE_U32]
    float* sB = smf + 2 * TILE_U32;       // [2][TILE_U32]
    const uint32_t sbase = smem_u32(smf);
    const uint32_t sAb   = sbase;
    const uint32_t sBb   = sbase + 2 * TILE_U32 * 4;

    const int tid  = threadIdx.x;
    const int wid  = tid >> 5;
    const int lane = tid & 31;
    const int g    = lane >> 2;
    const int t    = lane & 3;
    const int wm   = (wid & 1) * 64;
    const int wn   = (wid >> 1) * 32;
    const int bm   = blockIdx.y * 128;
    const int bn   = blockIdx.x * 128;

    // loader mapping: 4 float4 per thread per tile
    const int lc4   = (tid & 7) * 4;          // k word offset
    const int lrow0 = tid >> 3;               // +i*32
    uint32_t stob[4];                          // byte offsets in a tile
#pragma unroll
    for (int i = 0; i < 4; i++)
        stob[i] = (uint32_t)(((lrow0 + i * 32) * LDS_S + lc4) * 4);

    const int nk = K / 32;

    float bias0[4], bias1[4];
#pragma unroll
    for (int nt = 0; nt < 4; nt++) {
        int c = bn + wn + nt * 8 + 2 * t;
        bias0[nt] = bias[c];
        bias1[nt] = bias[c + 1];
    }

    float acc[4][4][4];
#pragma unroll
    for (int mt = 0; mt < 4; mt++)
#pragma unroll
        for (int nt = 0; nt < 4; nt++)
#pragma unroll
            for (int r = 0; r < 4; r++) acc[mt][nt][r] = 0.0f;

    const float* Arow = A + (size_t)(bm + lrow0) * K + lc4;
    const float* Brow = B + (size_t)(bn + lrow0) * K + lc4;

    // preload stage 0
#pragma unroll
    for (int i = 0; i < 4; i++) {
        CP_ASYNC16(sAb + stob[i], Arow + (size_t)(i * 32) * K);
        CP_ASYNC16(sBb + stob[i], Brow + (size_t)(i * 32) * K);
    }
    CP_COMMIT();

    // fragment base offsets (word units within a tile)
    uint32_t aoff[4], boff[4];
#pragma unroll
    for (int mt = 0; mt < 4; mt++) aoff[mt] = (uint32_t)((wm + mt * 16 + g) * LDS_S + t);
#pragma unroll
    for (int nt = 0; nt < 4; nt++) boff[nt] = (uint32_t)((wn + nt * 8 + g) * LDS_S + t);

    for (int kt = 0; kt < nk; kt++) {
        const int cur  = kt & 1;
        const bool more = (kt + 1 < nk);

        CP_WAIT0();
        __syncthreads();

        if (more) {
            const int nxt = cur ^ 1;
            const uint32_t dA = sAb + (uint32_t)nxt * TILE_U32 * 4;
            const uint32_t dB = sBb + (uint32_t)nxt * TILE_U32 * 4;
            const int ko = (kt + 1) * 32;
#pragma unroll
            for (int i = 0; i < 4; i++) {
                CP_ASYNC16(dA + stob[i], Arow + (size_t)(i * 32) * K + ko);
                CP_ASYNC16(dB + stob[i], Brow + (size_t)(i * 32) * K + ko);
            }
            CP_COMMIT();
        }

        const float* As = sA + cur * TILE_U32;
        const float* Bs = sB + cur * TILE_U32;
#pragma unroll
        for (int kk = 0; kk < 32; kk += 8) {
            uint32_t af[4][4], bf[4][2];
#pragma unroll
            for (int mt = 0; mt < 4; mt++) {
                const float* p = As + aoff[mt] + kk;
                af[mt][0] = f2tf32(p[0]);
                af[mt][1] = f2tf32(p[8 * LDS_S]);
                af[mt][2] = f2tf32(p[4]);
                af[mt][3] = f2tf32(p[8 * LDS_S + 4]);
            }
#pragma unroll
            for (int nt = 0; nt < 4; nt++) {
                const float* p = Bs + boff[nt] + kk;
                bf[nt][0] = f2tf32(p[0]);
                bf[nt][1] = f2tf32(p[4]);
            }
#pragma unroll
            for (int mt = 0; mt < 4; mt++)
#pragma unroll
                for (int nt = 0; nt < 4; nt++)
                    mma_tf32(acc[mt][nt], af[mt], bf[nt]);
        }
        __syncthreads();   // done reading 'cur' before next iter's cp.async overwrites it
    }

#pragma unroll
    for (int mt = 0; mt < 4; mt++) {
        const int r0 = bm + wm + mt * 16 + g;
#pragma unroll
        for (int nt = 0; nt < 4; nt++) {
            const int c0 = bn + wn + nt * 8 + 2 * t;
            float2 v0 = make_float2(acc[mt][nt][0] + bias0[nt],
                                    acc[mt][nt][1] + bias1[nt]);
            float2 v1 = make_float2(acc[mt][nt][2] + bias0[nt],
                                    acc[mt][nt][3] + bias1[nt]);
            *(float2*)(C + (size_t)r0 * N + c0)       = v0;
            *(float2*)(C + (size_t)(r0 + 8) * N + c0) = v1;
        }
    }
}

// ===========================================================================
// Tensor-core causal flash attention (unchanged from R4 — passing).
// ===========================================================================
#define LDK 68
#define LDV 72
#define LDSP 68
#define ATTN_SMEM ((64 * LDK + 64 * LDV + 64 * LDSP) * (int)sizeof(uint32_t)) // 53248

__global__ __launch_bounds__(128) void attn_mma_kernel(
    const float* __restrict__ qkv, float* __restrict__ out)
{
    extern __shared__ uint32_t smw[];
    uint32_t* Ks = smw;
    uint32_t* Vs = Ks + 64 * LDK;
    uint32_t* Ss = Vs + 64 * LDV;

    const int qt   = blockIdx.x;
    const int h    = blockIdx.y;
    const int b    = blockIdx.z;
    const int tid  = threadIdx.x;
    const int wid  = tid >> 5;
    const int lane = tid & 31;
    const int g    = lane >> 2;
    const int t    = lane & 3;
    const int r0   = wid * 16;
    const float scale = 0.125f;
    const size_t rstride = (size_t)E3;

    const float* qbase = qkv + ((size_t)b * S_LEN + (size_t)qt * 64) * rstride + h * HDIM;
#pragma unroll
    for (int i = 0; i < 8; i++) {
        int idx = tid + i * 128;
        int row = idx >> 4;
        int c4  = (idx & 15) * 4;
        float4 v = *(const float4*)(qbase + (size_t)row * rstride + c4);
        uint32_t* p = Ss + row * LDSP + c4;
        p[0] = f2tf32(v.x); p[1] = f2tf32(v.y);
        p[2] = f2tf32(v.z); p[3] = f2tf32(v.w);
    }
    __syncthreads();

    uint32_t qf[8][4];
#pragma unroll
    for (int ks = 0; ks < 8; ks++) {
        const uint32_t* p0 = Ss + (r0 + g) * LDSP + ks * 8 + t;
        const uint32_t* p1 = Ss + (r0 + g + 8) * LDSP + ks * 8 + t;
        qf[ks][0] = p0[0];
        qf[ks][1] = p1[0];
        qf[ks][2] = p0[4];
        qf[ks][3] = p1[4];
    }

    float m_lo = -CUDART_INF_F, m_hi = -CUDART_INF_F;
    float l_lo = 0.0f, l_hi = 0.0f;
    float oacc[8][4];
#pragma unroll
    for (int nt = 0; nt < 8; nt++)
#pragma unroll
        for (int r = 0; r < 4; r++) oacc[nt][r] = 0.0f;

    for (int kt = 0; kt <= qt; kt++) {
        __syncthreads();

        const float* kbase = qkv + ((size_t)b * S_LEN + (size_t)kt * 64) * rstride
                             + EMB + h * HDIM;
        const float* vbase = kbase + EMB;
#pragma unroll
        for (int i = 0; i < 8; i++) {
            int idx = tid + i * 128;
            int row = idx >> 4;
            int c4  = (idx & 15) * 4;
            float4 kv = *(const float4*)(kbase + (size_t)row * rstride + c4);
            uint32_t* pk = Ks + row * LDK + c4;
            pk[0] = f2tf32(kv.x); pk[1] = f2tf32(kv.y);
            pk[2] = f2tf32(kv.z); pk[3] = f2tf32(kv.w);
            float4 vv = *(const float4*)(vbase + (size_t)row * rstride + c4);
            uint32_t* pv = Vs + row * LDV + c4;
            pv[0] = f2tf32(vv.x); pv[1] = f2tf32(vv.y);
            pv[2] = f2tf32(vv.z); pv[3] = f2tf32(vv.w);
        }
        __syncthreads();

        float sacc[8][4];
#pragma unroll
        for (int nt = 0; nt < 8; nt++)
#pragma unroll
            for (int r = 0; r < 4; r++) sacc[nt][r] = 0.0f;

#pragma unroll
        for (int ks = 0; ks < 8; ks++) {
            const int kk = ks * 8;
#pragma unroll
            for (int nt = 0; nt < 8; nt++) {
                const uint32_t* pb = Ks + (nt * 8 + g) * LDK + kk + t;
                uint32_t bf[2] = { pb[0], pb[4] };
                mma_tf32(sacc[nt], qf[ks], bf);
            }
        }

        const bool diag = (kt == qt);
#pragma unroll
        for (int nt = 0; nt < 8; nt++) {
            const int c0 = nt * 8 + 2 * t;
#pragma unroll
            for (int r = 0; r < 4; r++) sacc[nt][r] *= scale;
            if (diag) {
                const int rlo = r0 + g, rhi = r0 + g + 8;
                if (c0 + 0 > rlo) sacc[nt][0] = -CUDART_INF_F;
                if (c0 + 1 > rlo) sacc[nt][1] = -CUDART_INF_F;
                if (c0 + 0 > rhi) sacc[nt][2] = -CUDART_INF_F;
                if (c0 + 1 > rhi) sacc[nt][3] = -CUDART_INF_F;
            }
        }

        float tmax_lo = -CUDART_INF_F, tmax_hi = -CUDART_INF_F;
#pragma unroll
        for (int nt = 0; nt < 8; nt++) {
            tmax_lo = fmaxf(tmax_lo, fmaxf(sacc[nt][0], sacc[nt][1]));
            tmax_hi = fmaxf(tmax_hi, fmaxf(sacc[nt][2], sacc[nt][3]));
        }
        tmax_lo = fmaxf(tmax_lo, __shfl_xor_sync(0xFFFFFFFF, tmax_lo, 1));
        tmax_lo = fmaxf(tmax_lo, __shfl_xor_sync(0xFFFFFFFF, tmax_lo, 2));
        tmax_hi = fmaxf(tmax_hi, __shfl_xor_sync(0xFFFFFFFF, tmax_hi, 1));
        tmax_hi = fmaxf(tmax_hi, __shfl_xor_sync(0xFFFFFFFF, tmax_hi, 2));

        const float mnew_lo = fmaxf(m_lo, tmax_lo);
        const float mnew_hi = fmaxf(m_hi, tmax_hi);
        const float alpha_lo = __expf(m_lo - mnew_lo);
        const float alpha_hi = __expf(m_hi - mnew_hi);

        float sum_lo = 0.0f, sum_hi = 0.0f;
        uint32_t* prow0 = Ss + (r0 + g) * LDSP;
        uint32_t* prow1 = Ss + (r0 + g + 8) * LDSP;
#pragma unroll
        for (int nt = 0; nt < 8; nt++) {
            const int c0 = nt * 8 + 2 * t;
            float p0 = __expf(sacc[nt][0] - mnew_lo);
            float p1 = __expf(sacc[nt][1] - mnew_lo);
            float p2 = __expf(sacc[nt][2] - mnew_hi);
            float p3 = __expf(sacc[nt][3] - mnew_hi);
            sum_lo += p0 + p1;
            sum_hi += p2 + p3;
            uint2 u0 = make_uint2(f2tf32(p0), f2tf32(p1));
            uint2 u1 = make_uint2(f2tf32(p2), f2tf32(p3));
            *(uint2*)(prow0 + c0) = u0;
            *(uint2*)(prow1 + c0) = u1;
        }
        sum_lo += __shfl_xor_sync(0xFFFFFFFF, sum_lo, 1);
        sum_lo += __shfl_xor_sync(0xFFFFFFFF, sum_lo, 2);
        sum_hi += __shfl_xor_sync(0xFFFFFFFF, sum_hi, 1);
        sum_hi += __shfl_xor_sync(0xFFFFFFFF, sum_hi, 2);

        l_lo = l_lo * alpha_lo + sum_lo;
        l_hi = l_hi * alpha_hi + sum_hi;
        m_lo = mnew_lo;
        m_hi = mnew_hi;

#pragma unroll
        for (int nt = 0; nt < 8; nt++) {
            oacc[nt][0] *= alpha_lo;
            oacc[nt][1] *= alpha_lo;
            oacc[nt][2] *= alpha_hi;
            oacc[nt][3] *= alpha_hi;
        }

        __syncwarp();

#pragma unroll
        for (int ks = 0; ks < 8; ks++) {
            const int kk = ks * 8;
            const uint32_t* pa0 = Ss + (r0 + g) * LDSP + kk + t;
            const uint32_t* pa1 = Ss + (r0 + g + 8) * LDSP + kk + t;
            uint32_t af[4] = { pa0[0], pa1[0], pa0[4], pa1[4] };
#pragma unroll
            for (int nt = 0; nt < 8; nt++) {
                const uint32_t* pb = Vs + (kk + t) * LDV + nt * 8 + g;
                uint32_t bf[2] = { pb[0], pb[4 * LDV] };
                mma_tf32(oacc[nt], af, bf);
            }
        }
    }

    const float inv_lo = 1.0f / l_lo;
    const float inv_hi = 1.0f / l_hi;
    float* obase = out + ((size_t)b * S_LEN + (size_t)qt * 64) * EMB + h * HDIM;
    float* orow0 = obase + (size_t)(r0 + g) * EMB;
    float* orow1 = obase + (size_t)(r0 + g + 8) * EMB;
#pragma unroll
    for (int nt = 0; nt < 8; nt++) {
        const int c0 = nt * 8 + 2 * t;
        *(float2*)(orow0 + c0) = make_float2(oacc[nt][0] * inv_lo, oacc[nt][1] * inv_lo);
        *(float2*)(orow1 + c0) = make_float2(oacc[nt][2] * inv_hi, oacc[nt][3] * inv_hi);
    }
}

// ===========================================================================
// Launch
// ===========================================================================
extern "C" void kernel_launch(void* const* d_in, const int* in_sizes, int n_in,
                              void* d_out, int out_size)
{
    const float* x     = (const float*)d_in[0];   // [4,2048,1024]
    const float* Wqkv  = (const float*)d_in[1];   // [3072,1024]
    const float* bqkv  = (const float*)d_in[2];   // [3072]
    const float* Wproj = (const float*)d_in[3];   // [1024,1024]
    const float* bproj = (const float*)d_in[4];   // [1024]
    float* out = (float*)d_out;                   // [4,2048,1024]

    float* qkv = nullptr;
    float* att = nullptr;
    cudaGetSymbolAddress((void**)&qkv, g_qkv);
    cudaGetSymbolAddress((void**)&att, g_att);

    cudaFuncSetAttribute(gemm_mma_tf32_nt_bias,
                         cudaFuncAttributeMaxDynamicSharedMemorySize, GEMM_SMEM);
    cudaFuncSetAttribute(attn_mma_kernel,
                         cudaFuncAttributeMaxDynamicSharedMemorySize, ATTN_SMEM);

    // 1) QKV GEMM (tf32 mma + cp.async): [8192,1024] @ [3072,1024]^T + b -> g_qkv
    {
        dim3 grid(E3 / 128, MTOT / 128);
        gemm_mma_tf32_nt_bias<<<grid, 256, GEMM_SMEM>>>(x, Wqkv, bqkv, qkv, MTOT, E3, EMB);
    }
    // 2) causal flash attention (tensor cores) -> g_att
    {
        dim3 grid(S_LEN / 64, NHEAD, BATCH);
        attn_mma_kernel<<<grid, 128, ATTN_SMEM>>>(qkv, att);
    }
    // 3) proj GEMM (tf32 mma + cp.async): [8192,1024] @ [1024,1024]^T + b -> out
    {
        dim3 grid(EMB / 128, MTOT / 128);
        gemm_mma_tf32_nt_bias<<<grid, 256, GEMM_SMEM>>>(att, Wproj, bproj, out, MTOT, EMB, EMB);
    }
}

// round 6
// speedup vs baseline: 7.8064x; 2.3999x over previous
#include <cuda_runtime.h>
#include <cuda_fp16.h>
#include <math_constants.h>
#include <cstdint>

// Problem constants
#define S_LEN   2048
#define EMB     1024
#define NHEAD   16
#define HDIM    64
#define BATCH   4
#define MTOT    (BATCH * S_LEN)        // 8192
#define E3      (3 * EMB)              // 3072

// Scratch (device globals — no allocations allowed)
__device__ __half g_hx [(size_t)MTOT * EMB];   // x in fp16
__device__ __half g_hw1[(size_t)E3 * EMB];     // W_qkv in fp16
__device__ __half g_hw2[(size_t)EMB * EMB];    // W_proj in fp16
__device__ __half g_qkv[(size_t)MTOT * E3];    // qkv (half)
__device__ __half g_att[(size_t)MTOT * EMB];   // attention out (half)

// ===========================================================================
// helpers
// ===========================================================================
__device__ __forceinline__ uint32_t smem_u32(const void* p) {
    uint32_t a;
    asm("{ .reg .u64 t; cvta.to.shared.u64 t, %1; cvt.u32.u64 %0, t; }"
        : "=r"(a) : "l"(p));
    return a;
}

__device__ __forceinline__ void mma_f16(float* d, const uint32_t* a,
                                        uint32_t b0, uint32_t b1) {
    asm volatile(
        "mma.sync.aligned.m16n8k16.row.col.f32.f16.f16.f32 "
        "{%0,%1,%2,%3}, {%4,%5,%6,%7}, {%8,%9}, {%0,%1,%2,%3};"
        : "+f"(d[0]), "+f"(d[1]), "+f"(d[2]), "+f"(d[3])
        : "r"(a[0]), "r"(a[1]), "r"(a[2]), "r"(a[3]), "r"(b0), "r"(b1));
}

#define LDM_X4(r, addr) \
    asm volatile("ldmatrix.sync.aligned.m8n8.x4.shared.b16 {%0,%1,%2,%3}, [%4];" \
        : "=r"((r)[0]), "=r"((r)[1]), "=r"((r)[2]), "=r"((r)[3]) : "r"(addr))
#define LDM_X4_T(r, addr) \
    asm volatile("ldmatrix.sync.aligned.m8n8.x4.trans.shared.b16 {%0,%1,%2,%3}, [%4];" \
        : "=r"((r)[0]), "=r"((r)[1]), "=r"((r)[2]), "=r"((r)[3]) : "r"(addr))

#define CP_ASYNC16(dst_u32, src_ptr) \
    asm volatile("cp.async.cg.shared.global [%0], [%1], 16;" \
                 :: "r"(dst_u32), "l"(src_ptr))
#define CP_COMMIT()  asm volatile("cp.async.commit_group;" ::: "memory")
#define CP_WAIT0()   asm volatile("cp.async.wait_group 0;" ::: "memory")

__device__ __forceinline__ uint32_t h2u(__half2 h) {
    return *reinterpret_cast<uint32_t*>(&h);
}

// ===========================================================================
// fp32 -> fp16 conversion (n multiple of 8)
// ===========================================================================
__global__ __launch_bounds__(256) void f32_to_f16(
    const float* __restrict__ s, __half* __restrict__ d, int n)
{
    int i = (blockIdx.x * blockDim.x + threadIdx.x) * 8;
    if (i < n) {
        float4 v0 = *(const float4*)(s + i);
        float4 v1 = *(const float4*)(s + i + 4);
        uint4 o;
        o.x = h2u(__float22half2_rn(make_float2(v0.x, v0.y)));
        o.y = h2u(__float22half2_rn(make_float2(v0.z, v0.w)));
        o.z = h2u(__float22half2_rn(make_float2(v1.x, v1.y)));
        o.w = h2u(__float22half2_rn(make_float2(v1.z, v1.w)));
        *(uint4*)(d + i) = o;
    }
}

// ===========================================================================
// fp16 mma.sync GEMM (NT): C[m][n] = sum_k A[m][k]*B[n][k] + bias[n]
// CTA 128x128, BK=64 halfs, 256 threads = 8 warps (warp 64x32), m16n8k16,
// ldmatrix fragments, double-buffered cp.async. HALF_OUT: C half else float.
// Requires M%128==0, N%128==0, K%64==0.
// ===========================================================================
// smem halfs: row stride 72 (64 data + 8 pad). A stage = 128*72*2 = 18432 B.
#define GST   18432                       // bytes per matrix-stage
#define GEMM_SMEM (4 * GST)               // 73728 B

template<int HALF_OUT>
__global__ __launch_bounds__(256, 2) void gemm_f16_nt_bias(
    const __half* __restrict__ A, const __half* __restrict__ B,
    const float* __restrict__ bias, void* __restrict__ Cv,
    int M, int N, int K)
{
    extern __shared__ __half smh[];
    const uint32_t sb = smem_u32(smh);
    // layout (bytes): A0 [0,GST), A1 [GST,2GST), B0 [2GST,3GST), B1 [3GST,4GST)

    const int tid  = threadIdx.x;
    const int wid  = tid >> 5;
    const int lane = tid & 31;
    const int g    = lane >> 2;
    const int t    = lane & 3;
    const int wm   = (wid & 1) * 64;
    const int wn   = (wid >> 1) * 32;
    const int bm   = blockIdx.y * 128;
    const int bn   = blockIdx.x * 128;

    // loader: 4 x 16B chunks per thread per matrix-stage
    const int lrow = tid >> 3;            // + i*32
    const int lch  = tid & 7;
    const __half* Arow = A + (size_t)(bm + lrow) * K + lch * 8;
    const __half* Brow = B + (size_t)(bn + lrow) * K + lch * 8;
    uint32_t ldst[4];
#pragma unroll
    for (int i = 0; i < 4; i++)
        ldst[i] = (uint32_t)((lrow + i * 32) * 144 + lch * 16);

    // ldmatrix per-lane bases (bytes)
    const uint32_t a_lm = sb +
        (uint32_t)(((wm + ((lane >> 3) & 1) * 8 + (lane & 7)) * 72 +
                    ((lane >> 4) & 1) * 8) * 2);
    const uint32_t b_lm = sb + 2 * GST +
        (uint32_t)(((wn + ((lane >> 4) & 1) * 8 + (lane & 7)) * 72 +
                    ((lane >> 3) & 1) * 8) * 2);

    float bias0[4], bias1[4];
#pragma unroll
    for (int nt = 0; nt < 4; nt++) {
        int c = bn + wn + nt * 8 + 2 * t;
        bias0[nt] = bias[c];
        bias1[nt] = bias[c + 1];
    }

    float acc[4][4][4];
#pragma unroll
    for (int mt = 0; mt < 4; mt++)
#pragma unroll
        for (int nt = 0; nt < 4; nt++)
#pragma unroll
            for (int r = 0; r < 4; r++) acc[mt][nt][r] = 0.0f;

    const int nk = K / 64;

    // preload stage 0
#pragma unroll
    for (int i = 0; i < 4; i++) {
        CP_ASYNC16(sb + ldst[i],           Arow + (size_t)(i * 32) * K);
        CP_ASYNC16(sb + 2 * GST + ldst[i], Brow + (size_t)(i * 32) * K);
    }
    CP_COMMIT();

    for (int kt = 0; kt < nk; kt++) {
        const int cur = kt & 1;
        CP_WAIT0();
        __syncthreads();

        if (kt + 1 < nk) {
            const int nxt = cur ^ 1;
            const int ko = (kt + 1) * 64;
            const uint32_t dA = sb + (uint32_t)nxt * GST;
            const uint32_t dB = sb + 2 * GST + (uint32_t)nxt * GST;
#pragma unroll
            for (int i = 0; i < 4; i++) {
                CP_ASYNC16(dA + ldst[i], Arow + (size_t)(i * 32) * K + ko);
                CP_ASYNC16(dB + ldst[i], Brow + (size_t)(i * 32) * K + ko);
            }
            CP_COMMIT();
        }

        const uint32_t aB = a_lm + (uint32_t)cur * GST;
        const uint32_t bB = b_lm + (uint32_t)cur * GST;
#pragma unroll
        for (int c = 0; c < 4; c++) {         // k chunk of 16 halfs
            uint32_t af[4][4], bfr[2][4];
#pragma unroll
            for (int mt = 0; mt < 4; mt++)
                LDM_X4(af[mt], aB + mt * 2304 + c * 32);
#pragma unroll
            for (int ntp = 0; ntp < 2; ntp++)
                LDM_X4(bfr[ntp], bB + ntp * 2304 + c * 32);
#pragma unroll
            for (int mt = 0; mt < 4; mt++)
#pragma unroll
                for (int nt = 0; nt < 4; nt++)
                    mma_f16(acc[mt][nt], af[mt],
                            bfr[nt >> 1][(nt & 1) * 2],
                            bfr[nt >> 1][(nt & 1) * 2 + 1]);
        }
    }

    // epilogue
#pragma unroll
    for (int mt = 0; mt < 4; mt++) {
        const int r0 = bm + wm + mt * 16 + g;
#pragma unroll
        for (int nt = 0; nt < 4; nt++) {
            const int c0 = bn + wn + nt * 8 + 2 * t;
            float v0 = acc[mt][nt][0] + bias0[nt];
            float v1 = acc[mt][nt][1] + bias1[nt];
            float v2 = acc[mt][nt][2] + bias0[nt];
            float v3 = acc[mt][nt][3] + bias1[nt];
            if (HALF_OUT) {
                __half* Ch = (__half*)Cv;
                *(__half2*)(Ch + (size_t)r0 * N + c0) =
                    __float22half2_rn(make_float2(v0, v1));
                *(__half2*)(Ch + (size_t)(r0 + 8) * N + c0) =
                    __float22half2_rn(make_float2(v2, v3));
            } else {
                float* Cf = (float*)Cv;
                *(float2*)(Cf + (size_t)r0 * N + c0)       = make_float2(v0, v1);
                *(float2*)(Cf + (size_t)(r0 + 8) * N + c0) = make_float2(v2, v3);
            }
        }
    }
}

// ===========================================================================
// fp16 tensor-core causal flash attention.
// Block = (q-tile 64, head, batch), 128 threads = 4 warps, warp = 16 q-rows.
// Q frags in regs; K via ldmatrix (non-trans); V via ldmatrix.trans;
// P stays in registers (acc layout == A-frag layout for m16n8k16).
// K/V double-buffered cp.async. One __syncthreads per KV tile.
// smem halfs, row stride 72: Q 9216B; K,V 2 stages each 9216B. Total 46080B.
// ===========================================================================
#define AST   9216
#define ATTN_SMEM (5 * AST)    // 46080

__global__ __launch_bounds__(128) void attn_f16_kernel(
    const __half* __restrict__ qkv, __half* __restrict__ out)
{
    extern __shared__ __half smh[];
    const uint32_t sb = smem_u32(smh);
    // bytes: Q [0,AST), K stage s [AST + s*AST), V stage s [3*AST + s*AST)

    const int qt   = blockIdx.x;
    const int h    = blockIdx.y;
    const int b    = blockIdx.z;
    const int tid  = threadIdx.x;
    const int wid  = tid >> 5;
    const int lane = tid & 31;
    const int g    = lane >> 2;
    const int t    = lane & 3;
    const int r0   = wid * 16;
    const float scale = 0.125f;

    // loader mapping: 4 x 16B chunks per thread per 64x64 half tile
    const int lrow = tid >> 3;            // + i*16
    const int lch  = tid & 7;
    uint32_t ldst[4];
#pragma unroll
    for (int i = 0; i < 4; i++)
        ldst[i] = (uint32_t)((lrow + i * 16) * 144 + lch * 16);

    const size_t bq = ((size_t)b * S_LEN + (size_t)qt * 64);
    const __half* Qg = qkv + (bq + lrow) * E3 + h * HDIM + lch * 8;

    // ldmatrix per-lane bases
    const uint32_t k_lm = sb + AST +
        (uint32_t)(((((lane >> 4) & 1) * 8 + (lane & 7)) * 72 +
                    ((lane >> 3) & 1) * 8) * 2);
    const uint32_t v_lm = sb + 3 * AST +
        (uint32_t)(((((lane >> 3) & 1) * 8 + (lane & 7)) * 72 +
                    ((lane >> 4) & 1) * 8) * 2);

    // prologue: load Q + K0 + V0
    {
        const size_t bk = (size_t)b * S_LEN;   // kt = 0
        const __half* Kg = qkv + (bk + lrow) * E3 + EMB + h * HDIM + lch * 8;
        const __half* Vg = Kg + EMB;
#pragma unroll
        for (int i = 0; i < 4; i++) {
            CP_ASYNC16(sb + ldst[i],           Qg + (size_t)(i * 16) * E3);
            CP_ASYNC16(sb + AST + ldst[i],     Kg + (size_t)(i * 16) * E3);
            CP_ASYNC16(sb + 3 * AST + ldst[i], Vg + (size_t)(i * 16) * E3);
        }
        CP_COMMIT();
        CP_WAIT0();
        __syncthreads();
    }

    // Q fragments (plain conflict-free LDS: bank = 4g+t)
    const uint32_t* Qw = (const uint32_t*)smh;
    uint32_t qf[4][4];
#pragma unroll
    for (int c = 0; c < 4; c++) {
        const uint32_t* p0 = Qw + (r0 + g) * 36 + c * 8 + t;
        const uint32_t* p1 = Qw + (r0 + g + 8) * 36 + c * 8 + t;
        qf[c][0] = p0[0];
        qf[c][1] = p1[0];
        qf[c][2] = p0[4];
        qf[c][3] = p1[4];
    }

    float m_lo = -CUDART_INF_F, m_hi = -CUDART_INF_F;
    float l_lo = 0.0f, l_hi = 0.0f;
    float oacc[8][4];
#pragma unroll
    for (int nt = 0; nt < 8; nt++)
#pragma unroll
        for (int r = 0; r < 4; r++) oacc[nt][r] = 0.0f;

    for (int kt = 0; kt <= qt; kt++) {
        const int cur  = kt & 1;
        const bool more = (kt < qt);

        // prefetch next K/V tile
        if (more) {
            const int nxt = cur ^ 1;
            const size_t bk = (size_t)b * S_LEN + (size_t)(kt + 1) * 64;
            const __half* Kg = qkv + (bk + lrow) * E3 + EMB + h * HDIM + lch * 8;
            const __half* Vg = Kg + EMB;
            const uint32_t dK = sb + AST + (uint32_t)nxt * AST;
            const uint32_t dV = sb + 3 * AST + (uint32_t)nxt * AST;
#pragma unroll
            for (int i = 0; i < 4; i++) {
                CP_ASYNC16(dK + ldst[i], Kg + (size_t)(i * 16) * E3);
                CP_ASYNC16(dV + ldst[i], Vg + (size_t)(i * 16) * E3);
            }
            CP_COMMIT();
        }

        // ---- S = Q K^T (16x64 per warp) ----
        const uint32_t kB = k_lm + (uint32_t)cur * AST;
        float sacc[8][4];
#pragma unroll
        for (int nt = 0; nt < 8; nt++)
#pragma unroll
            for (int r = 0; r < 4; r++) sacc[nt][r] = 0.0f;

#pragma unroll
        for (int c = 0; c < 4; c++) {
#pragma unroll
            for (int ntp = 0; ntp < 4; ntp++) {
                uint32_t bfr[4];
                LDM_X4(bfr, kB + ntp * 2304 + c * 32);
                mma_f16(sacc[2 * ntp + 0], qf[c], bfr[0], bfr[1]);
                mma_f16(sacc[2 * ntp + 1], qf[c], bfr[2], bfr[3]);
            }
        }

        // ---- scale + causal mask (diagonal tile only) ----
        const bool diag = (kt == qt);
#pragma unroll
        for (int nt = 0; nt < 8; nt++) {
            const int c0 = nt * 8 + 2 * t;
#pragma unroll
            for (int r = 0; r < 4; r++) sacc[nt][r] *= scale;
            if (diag) {
                const int rlo = r0 + g, rhi = r0 + g + 8;
                if (c0 + 0 > rlo) sacc[nt][0] = -CUDART_INF_F;
                if (c0 + 1 > rlo) sacc[nt][1] = -CUDART_INF_F;
                if (c0 + 0 > rhi) sacc[nt][2] = -CUDART_INF_F;
                if (c0 + 1 > rhi) sacc[nt][3] = -CUDART_INF_F;
            }
        }

        // ---- online softmax (quad shuffles) ----
        float tmax_lo = -CUDART_INF_F, tmax_hi = -CUDART_INF_F;
#pragma unroll
        for (int nt = 0; nt < 8; nt++) {
            tmax_lo = fmaxf(tmax_lo, fmaxf(sacc[nt][0], sacc[nt][1]));
            tmax_hi = fmaxf(tmax_hi, fmaxf(sacc[nt][2], sacc[nt][3]));
        }
        tmax_lo = fmaxf(tmax_lo, __shfl_xor_sync(0xFFFFFFFF, tmax_lo, 1));
        tmax_lo = fmaxf(tmax_lo, __shfl_xor_sync(0xFFFFFFFF, tmax_lo, 2));
        tmax_hi = fmaxf(tmax_hi, __shfl_xor_sync(0xFFFFFFFF, tmax_hi, 1));
        tmax_hi = fmaxf(tmax_hi, __shfl_xor_sync(0xFFFFFFFF, tmax_hi, 2));

        const float mnew_lo = fmaxf(m_lo, tmax_lo);
        const float mnew_hi = fmaxf(m_hi, tmax_hi);
        const float alpha_lo = __expf(m_lo - mnew_lo);
        const float alpha_hi = __expf(m_hi - mnew_hi);

        float sum_lo = 0.0f, sum_hi = 0.0f;
        uint32_t pa[8][2];   // P fragments: [nt][row g | row g+8]
#pragma unroll
        for (int nt = 0; nt < 8; nt++) {
            float p0 = __expf(sacc[nt][0] - mnew_lo);
            float p1 = __expf(sacc[nt][1] - mnew_lo);
            float p2 = __expf(sacc[nt][2] - mnew_hi);
            float p3 = __expf(sacc[nt][3] - mnew_hi);
            sum_lo += p0 + p1;
            sum_hi += p2 + p3;
            pa[nt][0] = h2u(__float22half2_rn(make_float2(p0, p1)));
            pa[nt][1] = h2u(__float22half2_rn(make_float2(p2, p3)));
        }
        sum_lo += __shfl_xor_sync(0xFFFFFFFF, sum_lo, 1);
        sum_lo += __shfl_xor_sync(0xFFFFFFFF, sum_lo, 2);
        sum_hi += __shfl_xor_sync(0xFFFFFFFF, sum_hi, 1);
        sum_hi += __shfl_xor_sync(0xFFFFFFFF, sum_hi, 2);

        l_lo = l_lo * alpha_lo + sum_lo;
        l_hi = l_hi * alpha_hi + sum_hi;
        m_lo = mnew_lo;
        m_hi = mnew_hi;

#pragma unroll
        for (int nt = 0; nt < 8; nt++) {
            oacc[nt][0] *= alpha_lo;
            oacc[nt][1] *= alpha_lo;
            oacc[nt][2] *= alpha_hi;
            oacc[nt][3] *= alpha_hi;
        }

        // ---- O += P V  (P from registers, V via ldmatrix.trans) ----
        const uint32_t vB = v_lm + (uint32_t)cur * AST;
#pragma unroll
        for (int c = 0; c < 4; c++) {         // k chunk over kv rows
            uint32_t af[4] = { pa[2 * c][0], pa[2 * c][1],
                               pa[2 * c + 1][0], pa[2 * c + 1][1] };
#pragma unroll
            for (int ntp = 0; ntp < 4; ntp++) {   // d tiles of 16
                uint32_t bfr[4];
                LDM_X4_T(bfr, vB + c * 2304 + ntp * 32);
                mma_f16(oacc[2 * ntp + 0], af, bfr[0], bfr[1]);
                mma_f16(oacc[2 * ntp + 1], af, bfr[2], bfr[3]);
            }
        }

        if (more) {
            CP_WAIT0();
            __syncthreads();
        }
    }

    // ---- epilogue: normalize + store half ----
    const float inv_lo = 1.0f / l_lo;
    const float inv_hi = 1.0f / l_hi;
    __half* obase = out + (bq) * EMB + h * HDIM;
    __half* orow0 = obase + (size_t)(r0 + g) * EMB;
    __half* orow1 = obase + (size_t)(r0 + g + 8) * EMB;
#pragma unroll
    for (int nt = 0; nt < 8; nt++) {
        const int c0 = nt * 8 + 2 * t;
        *(__half2*)(orow0 + c0) = __float22half2_rn(
            make_float2(oacc[nt][0] * inv_lo, oacc[nt][1] * inv_lo));
        *(__half2*)(orow1 + c0) = __float22half2_rn(
            make_float2(oacc[nt][2] * inv_hi, oacc[nt][3] * inv_hi));
    }
}

// ===========================================================================
// Launch
// ===========================================================================
extern "C" void kernel_launch(void* const* d_in, const int* in_sizes, int n_in,
                              void* d_out, int out_size)
{
    const float* x     = (const float*)d_in[0];   // [4,2048,1024]
    const float* Wqkv  = (const float*)d_in[1];   // [3072,1024]
    const float* bqkv  = (const float*)d_in[2];   // [3072]
    const float* Wproj = (const float*)d_in[3];   // [1024,1024]
    const float* bproj = (const float*)d_in[4];   // [1024]
    float* out = (float*)d_out;                   // [4,2048,1024]

    __half *hx, *hw1, *hw2, *qkv, *att;
    cudaGetSymbolAddress((void**)&hx,  g_hx);
    cudaGetSymbolAddress((void**)&hw1, g_hw1);
    cudaGetSymbolAddress((void**)&hw2, g_hw2);
    cudaGetSymbolAddress((void**)&qkv, g_qkv);
    cudaGetSymbolAddress((void**)&att, g_att);

    cudaFuncSetAttribute(gemm_f16_nt_bias<1>,
                         cudaFuncAttributeMaxDynamicSharedMemorySize, GEMM_SMEM);
    cudaFuncSetAttribute(gemm_f16_nt_bias<0>,
                         cudaFuncAttributeMaxDynamicSharedMemorySize, GEMM_SMEM);
    cudaFuncSetAttribute(attn_f16_kernel,
                         cudaFuncAttributeMaxDynamicSharedMemorySize, ATTN_SMEM);

    // 0) fp32 -> fp16 conversions
    f32_to_f16<<<(MTOT * EMB / 8 + 255) / 256, 256>>>(x, hx, MTOT * EMB);
    f32_to_f16<<<(E3 * EMB / 8 + 255) / 256, 256>>>(Wqkv, hw1, E3 * EMB);
    f32_to_f16<<<(EMB * EMB / 8 + 255) / 256, 256>>>(Wproj, hw2, EMB * EMB);

    // 1) QKV GEMM (fp16 mma, half out): [8192,1024] @ [3072,1024]^T + b
    {
        dim3 grid(E3 / 128, MTOT / 128);
        gemm_f16_nt_bias<1><<<grid, 256, GEMM_SMEM>>>(hx, hw1, bqkv, qkv,
                                                      MTOT, E3, EMB);
    }
    // 2) causal flash attention (fp16 tensor cores) -> g_att (half)
    {
        dim3 grid(S_LEN / 64, NHEAD, BATCH);
        attn_f16_kernel<<<grid, 128, ATTN_SMEM>>>(qkv, att);
    }
    // 3) proj GEMM (fp16 mma, float out): [8192,1024] @ [1024,1024]^T + b
    {
        dim3 grid(EMB / 128, MTOT / 128);
        gemm_f16_nt_bias<0><<<grid, 256, GEMM_SMEM>>>(att, hw2, bproj, out,
                                                      MTOT, EMB, EMB);
    }
}